// round 13
// baseline (speedup 1.0000x reference)
#include <cuda_runtime.h>
#include <cuda_fp16.h>
#include <cstdint>
#include <math.h>

// Problem constants
#define BSZ   8
#define TMAX  256
#define UMAX  64
#define EDIM  512
#define PDIM  512
#define JDIM  512
#define VDIM  1024
#define MAX_STU (BSZ * TMAX * UMAX)   // 131072

// -------- scratch (device globals) --------
__device__ float  g_emb_proj[VDIM * JDIM];            // 2 MB
__device__ float  g_enc_proj[2048 * JDIM];            // 4 MB
__device__ __half g_wjh[VDIM * JDIM];                 // 1 MB
__device__ __half g_embh[VDIM * PDIM];                // 1 MB
__device__ __half g_ench[2048 * EDIM];                // 2 MB
__device__ __half g_wpredh[JDIM * PDIM];              // 512 KB
__device__ __half g_wench[JDIM * EDIM];               // 512 KB
__device__ __half g_h[(size_t)MAX_STU * JDIM];        // 128 MB

__device__ __forceinline__ uint32_t smem_u32(const void* p) {
    uint32_t a;
    asm("{ .reg .u64 t; cvta.to.shared.u64 t, %1; cvt.u32.u64 %0, t; }" : "=r"(a) : "l"(p));
    return a;
}

#define LDSM_X4(r0, r1, r2, r3, addr) \
    asm volatile("ldmatrix.sync.aligned.m8n8.x4.shared.b16 {%0,%1,%2,%3}, [%4];" \
        : "=r"(r0), "=r"(r1), "=r"(r2), "=r"(r3) : "r"(addr))

#define MMA_F16(d, a, b0, b1) \
    asm volatile("mma.sync.aligned.m16n8k16.row.col.f32.f16.f16.f32 " \
        "{%0,%1,%2,%3}, {%4,%5,%6,%7}, {%8,%9}, {%0,%1,%2,%3};" \
        : "+f"((d)[0]), "+f"((d)[1]), "+f"((d)[2]), "+f"((d)[3]) \
        : "r"((a)[0]), "r"((a)[1]), "r"((a)[2]), "r"((a)[3]), \
          "r"(b0), "r"(b1))

// ====================================================================
// fp16 NT GEMM core, 128 threads: C[M,ldc] = A[M,512] @ B[*,512]^T + bias
// BM=128, BN=128, BK=64; 4 warps 2(m)x2(n); warp tile 64x64.
// 2-stage cp.async, 64 KB smem, 2 CTAs/SM.
// Fragment double-buffering: LDSM for ks+1 issued over MMAs of ks.
// ====================================================================
#define AT_HALVES 8192                        // 128*64
#define STAGE_HALVES (2 * AT_HALVES)
#define SM_GEMM_BYTES (2 * STAGE_HALVES * 2)  // 65536 B

__device__ __forceinline__ void gemm_f16_core(
    const __half* __restrict__ A, const __half* __restrict__ B,
    const float* __restrict__ bias, float* __restrict__ C,
    int M, int ldc, int bm, int bn, __half* smh)
{
    __half* Ab[2] = { smh, smh + STAGE_HALVES };
    __half* Bb[2] = { smh + AT_HALVES, smh + STAGE_HALVES + AT_HALVES };

    const int tid  = threadIdx.x;
    const int wid  = tid >> 5, lane = tid & 31;
    const int g    = lane >> 2, tg = lane & 3;
    const int wm   = (wid >> 1) * 64;      // 2 warp-rows
    const int wn   = (wid & 1) * 64;       // 2 warp-cols

    int arow_off[4], arow_sw[4], brow_off[4], brow_sw[4];
#pragma unroll
    for (int ma = 0; ma < 4; ma++) {
        int r = wm + ma * 16 + (lane & 15);
        arow_off[ma] = r * 64; arow_sw[ma] = r & 7;
    }
#pragma unroll
    for (int p = 0; p < 4; p++) {
        int r = wn + p * 16 + ((lane >> 4) << 3) + (lane & 7);
        brow_off[p] = r * 64; brow_sw[p] = r & 7;
    }
    const int acl = lane >> 4;
    const int bcl = (lane >> 3) & 1;

    float acc[4][8][4];
#pragma unroll
    for (int i = 0; i < 4; i++)
#pragma unroll
        for (int j = 0; j < 8; j++)
#pragma unroll
            for (int q = 0; q < 4; q++) acc[i][j][q] = 0.0f;

    auto load_tile = [&](int kt, int buf) {
        const int k0 = kt * 64;
#pragma unroll
        for (int t = 0; t < 8; t++) {       // A: 1024 chunks, 8/thread
            int i = tid + t * 128;
            int row = i >> 3, ch = i & 7;
            const __half* src = A + (size_t)(bm + row) * JDIM + k0 + ch * 8;
            uint32_t dst = smem_u32(&Ab[buf][row * 64 + ((ch ^ (row & 7)) * 8)]);
            int sz = (bm + row < M) ? 16 : 0;
            asm volatile("cp.async.ca.shared.global [%0], [%1], 16, %2;\n"
                         :: "r"(dst), "l"(src), "r"(sz));
        }
#pragma unroll
        for (int t = 0; t < 8; t++) {       // B: 1024 chunks, 8/thread
            int i = tid + t * 128;
            int row = i >> 3, ch = i & 7;
            const __half* src = B + (size_t)(bn + row) * JDIM + k0 + ch * 8;
            uint32_t dst = smem_u32(&Bb[buf][row * 64 + ((ch ^ (row & 7)) * 8)]);
            asm volatile("cp.async.ca.shared.global [%0], [%1], 16;\n"
                         :: "r"(dst), "l"(src));
        }
        asm volatile("cp.async.commit_group;\n" ::: "memory");
    };

    load_tile(0, 0);
    load_tile(1, 1);

    uint32_t af[2][4][4], bf[2][4][4];

    for (int kt = 0; kt < 8; kt++) {
        if (kt < 7) asm volatile("cp.async.wait_group 1;\n" ::: "memory");
        else        asm volatile("cp.async.wait_group 0;\n" ::: "memory");
        __syncthreads();

        const __half* As = Ab[kt & 1];
        const __half* Bs = Bb[kt & 1];

        // prime frags for ks=0
#pragma unroll
        for (int ma = 0; ma < 4; ma++) {
            uint32_t ad = smem_u32(&As[arow_off[ma] + ((acl ^ arow_sw[ma]) * 8)]);
            LDSM_X4(af[0][ma][0], af[0][ma][1], af[0][ma][2], af[0][ma][3], ad);
        }
#pragma unroll
        for (int p = 0; p < 4; p++) {
            uint32_t bd = smem_u32(&Bs[brow_off[p] + ((bcl ^ brow_sw[p]) * 8)]);
            LDSM_X4(bf[0][p][0], bf[0][p][1], bf[0][p][2], bf[0][p][3], bd);
        }

#pragma unroll
        for (int ks = 0; ks < 4; ks++) {
            const int cur = ks & 1, nxt = cur ^ 1;
            if (ks < 3) {
#pragma unroll
                for (int ma = 0; ma < 4; ma++) {
                    int ch = (ks + 1) * 2 + acl;
                    uint32_t ad = smem_u32(&As[arow_off[ma] + ((ch ^ arow_sw[ma]) * 8)]);
                    LDSM_X4(af[nxt][ma][0], af[nxt][ma][1], af[nxt][ma][2], af[nxt][ma][3], ad);
                }
#pragma unroll
                for (int p = 0; p < 4; p++) {
                    int ch = (ks + 1) * 2 + bcl;
                    uint32_t bd = smem_u32(&Bs[brow_off[p] + ((ch ^ brow_sw[p]) * 8)]);
                    LDSM_X4(bf[nxt][p][0], bf[nxt][p][1], bf[nxt][p][2], bf[nxt][p][3], bd);
                }
            }
#pragma unroll
            for (int ma = 0; ma < 4; ma++)
#pragma unroll
                for (int p = 0; p < 4; p++) {
                    MMA_F16(acc[ma][2 * p + 0], af[cur][ma], bf[cur][p][0], bf[cur][p][1]);
                    MMA_F16(acc[ma][2 * p + 1], af[cur][ma], bf[cur][p][2], bf[cur][p][3]);
                }
        }
        __syncthreads();
        if (kt + 2 < 8) load_tile(kt + 2, kt & 1);
    }

    // epilogue
#pragma unroll
    for (int ma = 0; ma < 4; ma++) {
        const int r0 = bm + wm + ma * 16 + g;
#pragma unroll
        for (int nb = 0; nb < 8; nb++) {
            const int col = bn + wn + nb * 8 + 2 * tg;
            float2 bv = make_float2(0.f, 0.f);
            if (bias) bv = *(const float2*)(bias + col);
            if (r0 < M) {
                float2 o = make_float2(acc[ma][nb][0] + bv.x, acc[ma][nb][1] + bv.y);
                *(float2*)(C + (size_t)r0 * ldc + col) = o;
            }
            if (r0 + 8 < M) {
                float2 o = make_float2(acc[ma][nb][2] + bv.x, acc[ma][nb][3] + bv.y);
                *(float2*)(C + (size_t)(r0 + 8) * ldc + col) = o;
            }
        }
    }
}

// ---- K4: join GEMM (N=1024). x = N-block (fast, L2 A-reuse), y = M-block.
__global__ __launch_bounds__(128, 2) void join_gemm_f16(
    const __half* __restrict__ A, const __half* __restrict__ B,
    const float* __restrict__ bias, float* __restrict__ C, int M)
{
    extern __shared__ __half smh[];
    gemm_f16_core(A, B, bias, C, M, VDIM, blockIdx.y * 128, blockIdx.x * 128, smh);
}

// ---- K1+K2: projection GEMMs (N=512), z selects problem.
__global__ __launch_bounds__(128, 2) void proj_gemm_dual(
    const __half* __restrict__ A0, const __half* __restrict__ B0,
    const float* __restrict__ bias0, float* __restrict__ C0, int M0,
    const __half* __restrict__ A1, const __half* __restrict__ B1,
    const float* __restrict__ bias1, float* __restrict__ C1, int M1)
{
    extern __shared__ __half smh[];
    const __half* A; const __half* B; const float* bias; float* C; int M;
    if (blockIdx.z == 0) { A = A0; B = B0; bias = bias0; C = C0; M = M0; }
    else                 { A = A1; B = B1; bias = bias1; C = C1; M = M1; }
    int bm = blockIdx.y * 128;
    if (bm >= M) return;
    gemm_f16_core(A, B, bias, C, M, JDIM, bm, blockIdx.x * 128, smh);
}

// ---------------- gather + add + tanh.approx -> fp16 h ----------------
__device__ __forceinline__ float tanh_fast(float x) {
    float r; asm("tanh.approx.f32 %0, %1;" : "=f"(r) : "f"(x)); return r;
}

__global__ __launch_bounds__(256) void build_h_kernel(
    const int* __restrict__ gidx, const int* __restrict__ prefix,
    const float* __restrict__ enc_proj, const float* __restrict__ emb_proj,
    const float* __restrict__ b_pred, __half* __restrict__ h, int STU)
{
    int row = blockIdx.x * 2 + (threadIdx.x >> 7);
    if (row >= STU) return;
    int j = threadIdx.x & 127;

    int idx = __ldg(gidx + row);
    int b = idx / (TMAX * UMAX);
    int rem = idx - b * (TMAX * UMAX);
    int t = rem / UMAX;
    int u = rem - t * UMAX;
    int tok = __ldg(prefix + b * UMAX + u);

    const float4* er = (const float4*)(enc_proj + ((size_t)b * TMAX + t) * JDIM);
    const float4* pr = (const float4*)(emb_proj + (size_t)tok * JDIM);
    const float4* bp = (const float4*)b_pred;
    __half2* hr = (__half2*)(h + (size_t)row * JDIM);

    float4 e = er[j], p = pr[j], bb = bp[j];
    float2 lo = make_float2(tanh_fast(e.x + p.x + bb.x), tanh_fast(e.y + p.y + bb.y));
    float2 hi = make_float2(tanh_fast(e.z + p.z + bb.z), tanh_fast(e.w + p.w + bb.w));
    hr[2 * j + 0] = __float22half2_rn(lo);
    hr[2 * j + 1] = __float22half2_rn(hi);
}

// ---------------- batched fp32 -> fp16 conversion of 5 tensors ----------------
__global__ __launch_bounds__(256) void cvt5_kernel(
    const float* __restrict__ wj,  __half* __restrict__ wj_o,
    const float* __restrict__ em,  __half* __restrict__ em_o,
    const float* __restrict__ en,  __half* __restrict__ en_o,
    const float* __restrict__ wp,  __half* __restrict__ wp_o,
    const float* __restrict__ we,  __half* __restrict__ we_o)
{
    int i = blockIdx.x * blockDim.x + threadIdx.x;   // float4 index
    const float* src; __half* dst; int loc;
    if      (i < 131072) { src = wj; dst = wj_o; loc = i; }
    else if (i < 262144) { src = em; dst = em_o; loc = i - 131072; }
    else if (i < 524288) { src = en; dst = en_o; loc = i - 262144; }
    else if (i < 589824) { src = wp; dst = wp_o; loc = i - 524288; }
    else if (i < 655360) { src = we; dst = we_o; loc = i - 589824; }
    else return;

    float4 v = ((const float4*)src)[loc];
    __half2* o = (__half2*)(dst + 4 * (size_t)loc);
    o[0] = __float22half2_rn(make_float2(v.x, v.y));
    o[1] = __float22half2_rn(make_float2(v.z, v.w));
}

// ----------------------------------------------------------------
extern "C" void kernel_launch(void* const* d_in, const int* in_sizes, int n_in,
                              void* d_out, int out_size)
{
    const float* enc_out = (const float*)d_in[0];
    const int*   prefix  = (const int*)  d_in[1];
    const int*   gidx    = (const int*)  d_in[4];
    const float* emb     = (const float*)d_in[5];
    const float* W_enc   = (const float*)d_in[6];
    const float* b_enc   = (const float*)d_in[7];
    const float* W_pred  = (const float*)d_in[8];
    const float* b_pred  = (const float*)d_in[9];
    const float* W_join  = (const float*)d_in[10];
    const float* b_join  = (const float*)d_in[11];
    float* out = (float*)d_out;

    const int STU = in_sizes[4];

    float  *p_emb_proj, *p_enc_proj;
    __half *p_h, *p_wjh, *p_embh, *p_ench, *p_wpredh, *p_wench;
    cudaGetSymbolAddress((void**)&p_emb_proj, g_emb_proj);
    cudaGetSymbolAddress((void**)&p_enc_proj, g_enc_proj);
    cudaGetSymbolAddress((void**)&p_h,        g_h);
    cudaGetSymbolAddress((void**)&p_wjh,      g_wjh);
    cudaGetSymbolAddress((void**)&p_embh,     g_embh);
    cudaGetSymbolAddress((void**)&p_ench,     g_ench);
    cudaGetSymbolAddress((void**)&p_wpredh,   g_wpredh);
    cudaGetSymbolAddress((void**)&p_wench,    g_wench);

    cudaFuncSetAttribute(join_gemm_f16,
                         cudaFuncAttributeMaxDynamicSharedMemorySize, SM_GEMM_BYTES);
    cudaFuncSetAttribute(proj_gemm_dual,
                         cudaFuncAttributeMaxDynamicSharedMemorySize, SM_GEMM_BYTES);

    // K0: convert all fp32 operands to fp16 in one pass
    cvt5_kernel<<<(655360 + 255) / 256, 256>>>(
        W_join, p_wjh, emb, p_embh, enc_out, p_ench,
        W_pred, p_wpredh, W_enc, p_wench);

    // K1+K2: emb_proj = emb@W_pred^T ; enc_proj = enc_out@W_enc^T + b_enc
    proj_gemm_dual<<<dim3(JDIM / 128, 16, 2), 128, SM_GEMM_BYTES>>>(
        p_embh, p_wpredh, nullptr, p_emb_proj, VDIM,
        p_ench, p_wench,  b_enc,   p_enc_proj, BSZ * TMAX);

    // K3: gather + tanh -> h fp16
    build_h_kernel<<<(STU + 1) / 2, 256>>>(gidx, prefix, p_enc_proj, p_emb_proj,
                                           b_pred, p_h, STU);

    // K4: logits = h @ W_join^T + b_join
    dim3 grid(VDIM / 128, (STU + 127) / 128);
    join_gemm_f16<<<grid, 128, SM_GEMM_BYTES>>>(p_h, p_wjh, b_join, out, STU);
}

// round 14
// speedup vs baseline: 1.0639x; 1.0639x over previous
#include <cuda_runtime.h>
#include <cuda_fp16.h>
#include <cstdint>
#include <math.h>

// Problem constants
#define BSZ   8
#define TMAX  256
#define UMAX  64
#define EDIM  512
#define PDIM  512
#define JDIM  512
#define VDIM  1024
#define MAX_STU (BSZ * TMAX * UMAX)   // 131072

// -------- scratch (device globals) --------
__device__ float  g_emb_proj[VDIM * JDIM];            // 2 MB
__device__ float  g_enc_proj[2048 * JDIM];            // 4 MB
__device__ __half g_wjh[VDIM * JDIM];                 // 1 MB
__device__ __half g_embh[VDIM * PDIM];                // 1 MB
__device__ __half g_ench[2048 * EDIM];                // 2 MB
__device__ __half g_wpredh[JDIM * PDIM];              // 512 KB
__device__ __half g_wench[JDIM * EDIM];               // 512 KB
__device__ __half g_h[(size_t)MAX_STU * JDIM];        // 128 MB

__device__ __forceinline__ uint32_t smem_u32(const void* p) {
    uint32_t a;
    asm("{ .reg .u64 t; cvta.to.shared.u64 t, %1; cvt.u32.u64 %0, t; }" : "=r"(a) : "l"(p));
    return a;
}

#define LDSM_X4(r0, r1, r2, r3, addr) \
    asm volatile("ldmatrix.sync.aligned.m8n8.x4.shared.b16 {%0,%1,%2,%3}, [%4];" \
        : "=r"(r0), "=r"(r1), "=r"(r2), "=r"(r3) : "r"(addr))

#define MMA_F16(d, a, b0, b1) \
    asm volatile("mma.sync.aligned.m16n8k16.row.col.f32.f16.f16.f32 " \
        "{%0,%1,%2,%3}, {%4,%5,%6,%7}, {%8,%9}, {%0,%1,%2,%3};" \
        : "+f"((d)[0]), "+f"((d)[1]), "+f"((d)[2]), "+f"((d)[3]) \
        : "r"((a)[0]), "r"((a)[1]), "r"((a)[2]), "r"((a)[3]), \
          "r"(b0), "r"(b1))

// ====================================================================
// fp16 NT GEMM core, 128 threads: C[M,ldc] = A[M,512] @ B[*,512]^T + bias
// BM=128, BN=128, BK=64; 4 warps 2(m)x2(n); warp tile 64x64.
// 2-stage cp.async.cg (L1 bypass), 64 KB smem, 2 CTAs/SM.
// ====================================================================
#define AT_HALVES 8192                        // 128*64
#define STAGE_HALVES (2 * AT_HALVES)
#define SM_GEMM_BYTES (2 * STAGE_HALVES * 2)  // 65536 B

__device__ __forceinline__ void gemm_f16_core(
    const __half* __restrict__ A, const __half* __restrict__ B,
    const float* __restrict__ bias, float* __restrict__ C,
    int M, int ldc, int bm, int bn, __half* smh)
{
    __half* Ab[2] = { smh, smh + STAGE_HALVES };
    __half* Bb[2] = { smh + AT_HALVES, smh + STAGE_HALVES + AT_HALVES };

    const int tid  = threadIdx.x;
    const int wid  = tid >> 5, lane = tid & 31;
    const int g    = lane >> 2, tg = lane & 3;
    const int wm   = (wid >> 1) * 64;      // 2 warp-rows
    const int wn   = (wid & 1) * 64;       // 2 warp-cols

    int arow_off[4], arow_sw[4], brow_off[4], brow_sw[4];
#pragma unroll
    for (int ma = 0; ma < 4; ma++) {
        int r = wm + ma * 16 + (lane & 15);
        arow_off[ma] = r * 64; arow_sw[ma] = r & 7;
    }
#pragma unroll
    for (int p = 0; p < 4; p++) {
        int r = wn + p * 16 + ((lane >> 4) << 3) + (lane & 7);
        brow_off[p] = r * 64; brow_sw[p] = r & 7;
    }
    const int acl = lane >> 4;
    const int bcl = (lane >> 3) & 1;

    float acc[4][8][4];
#pragma unroll
    for (int i = 0; i < 4; i++)
#pragma unroll
        for (int j = 0; j < 8; j++)
#pragma unroll
            for (int q = 0; q < 4; q++) acc[i][j][q] = 0.0f;

    auto load_tile = [&](int kt, int buf) {
        const int k0 = kt * 64;
#pragma unroll
        for (int t = 0; t < 8; t++) {       // A: 1024 chunks, 8/thread
            int i = tid + t * 128;
            int row = i >> 3, ch = i & 7;
            const __half* src = A + (size_t)(bm + row) * JDIM + k0 + ch * 8;
            uint32_t dst = smem_u32(&Ab[buf][row * 64 + ((ch ^ (row & 7)) * 8)]);
            int sz = (bm + row < M) ? 16 : 0;
            asm volatile("cp.async.cg.shared.global [%0], [%1], 16, %2;\n"
                         :: "r"(dst), "l"(src), "r"(sz));
        }
#pragma unroll
        for (int t = 0; t < 8; t++) {       // B: 1024 chunks, 8/thread
            int i = tid + t * 128;
            int row = i >> 3, ch = i & 7;
            const __half* src = B + (size_t)(bn + row) * JDIM + k0 + ch * 8;
            uint32_t dst = smem_u32(&Bb[buf][row * 64 + ((ch ^ (row & 7)) * 8)]);
            asm volatile("cp.async.cg.shared.global [%0], [%1], 16;\n"
                         :: "r"(dst), "l"(src));
        }
        asm volatile("cp.async.commit_group;\n" ::: "memory");
    };

    load_tile(0, 0);
    load_tile(1, 1);

#pragma unroll
    for (int kt = 0; kt < 8; kt++) {
        if (kt < 7) asm volatile("cp.async.wait_group 1;\n" ::: "memory");
        else        asm volatile("cp.async.wait_group 0;\n" ::: "memory");
        __syncthreads();

        const __half* As = Ab[kt & 1];
        const __half* Bs = Bb[kt & 1];
#pragma unroll
        for (int ks = 0; ks < 4; ks++) {
            uint32_t a[4][4], b[4][4];
#pragma unroll
            for (int ma = 0; ma < 4; ma++) {
                int ch = ks * 2 + acl;
                uint32_t ad = smem_u32(&As[arow_off[ma] + ((ch ^ arow_sw[ma]) * 8)]);
                LDSM_X4(a[ma][0], a[ma][1], a[ma][2], a[ma][3], ad);
            }
#pragma unroll
            for (int p = 0; p < 4; p++) {
                int ch = ks * 2 + bcl;
                uint32_t bd = smem_u32(&Bs[brow_off[p] + ((ch ^ brow_sw[p]) * 8)]);
                LDSM_X4(b[p][0], b[p][1], b[p][2], b[p][3], bd);
            }
#pragma unroll
            for (int ma = 0; ma < 4; ma++)
#pragma unroll
                for (int p = 0; p < 4; p++) {
                    MMA_F16(acc[ma][2 * p + 0], a[ma], b[p][0], b[p][1]);
                    MMA_F16(acc[ma][2 * p + 1], a[ma], b[p][2], b[p][3]);
                }
        }
        __syncthreads();
        if (kt + 2 < 8) load_tile(kt + 2, kt & 1);
    }

    // epilogue
#pragma unroll
    for (int ma = 0; ma < 4; ma++) {
        const int r0 = bm + wm + ma * 16 + g;
#pragma unroll
        for (int nb = 0; nb < 8; nb++) {
            const int col = bn + wn + nb * 8 + 2 * tg;
            float2 bv = make_float2(0.f, 0.f);
            if (bias) bv = *(const float2*)(bias + col);
            if (r0 < M) {
                float2 o = make_float2(acc[ma][nb][0] + bv.x, acc[ma][nb][1] + bv.y);
                *(float2*)(C + (size_t)r0 * ldc + col) = o;
            }
            if (r0 + 8 < M) {
                float2 o = make_float2(acc[ma][nb][2] + bv.x, acc[ma][nb][3] + bv.y);
                *(float2*)(C + (size_t)(r0 + 8) * ldc + col) = o;
            }
        }
    }
}

// ---- K4: join GEMM (N=1024). x = N-block (fast, L2 A-reuse), y = M-block.
__global__ __launch_bounds__(128, 2) void join_gemm_f16(
    const __half* __restrict__ A, const __half* __restrict__ B,
    const float* __restrict__ bias, float* __restrict__ C, int M)
{
    extern __shared__ __half smh[];
    gemm_f16_core(A, B, bias, C, M, VDIM, blockIdx.y * 128, blockIdx.x * 128, smh);
}

// ---- K1+K2: projection GEMMs (N=512), z selects problem.
__global__ __launch_bounds__(128, 2) void proj_gemm_dual(
    const __half* __restrict__ A0, const __half* __restrict__ B0,
    const float* __restrict__ bias0, float* __restrict__ C0, int M0,
    const __half* __restrict__ A1, const __half* __restrict__ B1,
    const float* __restrict__ bias1, float* __restrict__ C1, int M1)
{
    extern __shared__ __half smh[];
    const __half* A; const __half* B; const float* bias; float* C; int M;
    if (blockIdx.z == 0) { A = A0; B = B0; bias = bias0; C = C0; M = M0; }
    else                 { A = A1; B = B1; bias = bias1; C = C1; M = M1; }
    int bm = blockIdx.y * 128;
    if (bm >= M) return;
    gemm_f16_core(A, B, bias, C, M, JDIM, bm, blockIdx.x * 128, smh);
}

// ---------------- gather + add + tanh.approx -> fp16 h ----------------
__device__ __forceinline__ float tanh_fast(float x) {
    float r; asm("tanh.approx.f32 %0, %1;" : "=f"(r) : "f"(x)); return r;
}

__global__ __launch_bounds__(256) void build_h_kernel(
    const int* __restrict__ gidx, const int* __restrict__ prefix,
    const float* __restrict__ enc_proj, const float* __restrict__ emb_proj,
    const float* __restrict__ b_pred, __half* __restrict__ h, int STU)
{
    int row = blockIdx.x * 2 + (threadIdx.x >> 7);
    if (row >= STU) return;
    int j = threadIdx.x & 127;

    int idx = __ldg(gidx + row);
    int b = idx / (TMAX * UMAX);
    int rem = idx - b * (TMAX * UMAX);
    int t = rem / UMAX;
    int u = rem - t * UMAX;
    int tok = __ldg(prefix + b * UMAX + u);

    const float4* er = (const float4*)(enc_proj + ((size_t)b * TMAX + t) * JDIM);
    const float4* pr = (const float4*)(emb_proj + (size_t)tok * JDIM);
    const float4* bp = (const float4*)b_pred;
    __half2* hr = (__half2*)(h + (size_t)row * JDIM);

    float4 e = er[j], p = pr[j], bb = bp[j];
    float2 lo = make_float2(tanh_fast(e.x + p.x + bb.x), tanh_fast(e.y + p.y + bb.y));
    float2 hi = make_float2(tanh_fast(e.z + p.z + bb.z), tanh_fast(e.w + p.w + bb.w));
    hr[2 * j + 0] = __float22half2_rn(lo);
    hr[2 * j + 1] = __float22half2_rn(hi);
}

// ---------------- batched fp32 -> fp16 conversion of 5 tensors ----------------
__global__ __launch_bounds__(256) void cvt5_kernel(
    const float* __restrict__ wj,  __half* __restrict__ wj_o,
    const float* __restrict__ em,  __half* __restrict__ em_o,
    const float* __restrict__ en,  __half* __restrict__ en_o,
    const float* __restrict__ wp,  __half* __restrict__ wp_o,
    const float* __restrict__ we,  __half* __restrict__ we_o)
{
    int i = blockIdx.x * blockDim.x + threadIdx.x;   // float4 index
    const float* src; __half* dst; int loc;
    if      (i < 131072) { src = wj; dst = wj_o; loc = i; }
    else if (i < 262144) { src = em; dst = em_o; loc = i - 131072; }
    else if (i < 524288) { src = en; dst = en_o; loc = i - 262144; }
    else if (i < 589824) { src = wp; dst = wp_o; loc = i - 524288; }
    else if (i < 655360) { src = we; dst = we_o; loc = i - 589824; }
    else return;

    float4 v = ((const float4*)src)[loc];
    __half2* o = (__half2*)(dst + 4 * (size_t)loc);
    o[0] = __float22half2_rn(make_float2(v.x, v.y));
    o[1] = __float22half2_rn(make_float2(v.z, v.w));
}

// ----------------------------------------------------------------
extern "C" void kernel_launch(void* const* d_in, const int* in_sizes, int n_in,
                              void* d_out, int out_size)
{
    const float* enc_out = (const float*)d_in[0];
    const int*   prefix  = (const int*)  d_in[1];
    const int*   gidx    = (const int*)  d_in[4];
    const float* emb     = (const float*)d_in[5];
    const float* W_enc   = (const float*)d_in[6];
    const float* b_enc   = (const float*)d_in[7];
    const float* W_pred  = (const float*)d_in[8];
    const float* b_pred  = (const float*)d_in[9];
    const float* W_join  = (const float*)d_in[10];
    const float* b_join  = (const float*)d_in[11];
    float* out = (float*)d_out;

    const int STU = in_sizes[4];

    float  *p_emb_proj, *p_enc_proj;
    __half *p_h, *p_wjh, *p_embh, *p_ench, *p_wpredh, *p_wench;
    cudaGetSymbolAddress((void**)&p_emb_proj, g_emb_proj);
    cudaGetSymbolAddress((void**)&p_enc_proj, g_enc_proj);
    cudaGetSymbolAddress((void**)&p_h,        g_h);
    cudaGetSymbolAddress((void**)&p_wjh,      g_wjh);
    cudaGetSymbolAddress((void**)&p_embh,     g_embh);
    cudaGetSymbolAddress((void**)&p_ench,     g_ench);
    cudaGetSymbolAddress((void**)&p_wpredh,   g_wpredh);
    cudaGetSymbolAddress((void**)&p_wench,    g_wench);

    cudaFuncSetAttribute(join_gemm_f16,
                         cudaFuncAttributeMaxDynamicSharedMemorySize, SM_GEMM_BYTES);
    cudaFuncSetAttribute(proj_gemm_dual,
                         cudaFuncAttributeMaxDynamicSharedMemorySize, SM_GEMM_BYTES);

    // K0: convert all fp32 operands to fp16 in one pass
    cvt5_kernel<<<(655360 + 255) / 256, 256>>>(
        W_join, p_wjh, emb, p_embh, enc_out, p_ench,
        W_pred, p_wpredh, W_enc, p_wench);

    // K1+K2: emb_proj = emb@W_pred^T ; enc_proj = enc_out@W_enc^T + b_enc
    proj_gemm_dual<<<dim3(JDIM / 128, 16, 2), 128, SM_GEMM_BYTES>>>(
        p_embh, p_wpredh, nullptr, p_emb_proj, VDIM,
        p_ench, p_wench,  b_enc,   p_enc_proj, BSZ * TMAX);

    // K3: gather + tanh -> h fp16
    build_h_kernel<<<(STU + 1) / 2, 256>>>(gidx, prefix, p_enc_proj, p_emb_proj,
                                           b_pred, p_h, STU);

    // K4: logits = h @ W_join^T + b_join
    dim3 grid(VDIM / 128, (STU + 127) / 128);
    join_gemm_f16<<<grid, 128, SM_GEMM_BYTES>>>(p_h, p_wjh, b_join, out, STU);
}